// round 1
// baseline (speedup 1.0000x reference)
#include <cuda_runtime.h>

// Problem constants (fixed by setup_inputs)
constexpr int ND    = 1024;   // N
constexpr int BSZ   = 2048;   // batch
constexpr int ITERS = 25;     // num_itr (host-known; device scalar ignored)

// ---------------------------------------------------------------------------
// Scratch (device globals — no allocation allowed)
// ---------------------------------------------------------------------------
__device__ float g_invM[ND * ND];
__device__ float g_T   [ND * ND];
__device__ float g_W   [ND * ND];
__device__ float g_yMF [BSZ * ND];
__device__ float g_c   [BSZ * ND];
__device__ float g_s0  [BSZ * ND];

// ---------------------------------------------------------------------------
// Triangular inverse of M = inv_omega*D + L (lower triangular), warp/column.
// Left-looking forward substitution; column j solved by one warp in shared.
// ---------------------------------------------------------------------------
__global__ void trinv_kernel(const float* __restrict__ A,
                             const float* __restrict__ iwp,
                             float* __restrict__ invM) {
    __shared__ float xs[4][ND];
    const int warp = threadIdx.x >> 5;
    const int lane = threadIdx.x & 31;
    const int j = blockIdx.x * 4 + warp;
    const float iw = *iwp;
    float* x = xs[warp];

    if (lane == 0) x[j] = 1.0f / (iw * A[(size_t)j * ND + j]);
    __syncwarp();

    for (int i = j + 1; i < ND; i++) {
        const float* Ai = A + (size_t)i * ND;
        float sum = 0.f;
        for (int k = j + lane; k < i; k += 32) sum += Ai[k] * x[k];
        #pragma unroll
        for (int o = 16; o > 0; o >>= 1) sum += __shfl_xor_sync(0xffffffffu, sum, o);
        if (lane == 0) x[i] = -sum / (iw * Ai[i]);
        __syncwarp();
    }
    for (int i = lane; i < ND; i += 32)
        invM[(size_t)i * ND + j] = (i < j) ? 0.f : x[i];
}

// T = (inv_omega - 1)*D - U  (upper-triangular + diagonal; zero below diag)
__global__ void build_T_kernel(const float* __restrict__ A,
                               const float* __restrict__ iwp) {
    const int i = blockIdx.x;
    const float iw = *iwp;
    for (int jj = threadIdx.x; jj < ND; jj += blockDim.x) {
        float v = 0.f;
        if (jj == i)      v = (iw - 1.f) * A[(size_t)i * ND + i];
        else if (jj > i)  v = -A[(size_t)i * ND + jj];
        g_T[(size_t)i * ND + jj] = v;
    }
}

// s0 = yMF / diag(A)   (broadcast divide along rows)
__global__ void s0_kernel(const float* __restrict__ A) {
    const int idx = blockIdx.x * blockDim.x + threadIdx.x;
    const int col = idx & (ND - 1);
    g_s0[idx] = g_yMF[idx] / A[(size_t)col * ND + col];
}

__global__ void zero_kernel(float4* __restrict__ p) {
    const size_t idx = (size_t)blockIdx.x * blockDim.x + threadIdx.x;
    p[idx] = make_float4(0.f, 0.f, 0.f, 0.f);
}

// ---------------------------------------------------------------------------
// fp32 SIMT GEMM: C = A @ B' (+ Cadd), optional dual write C2.
//   TRANSB=false: B'[k][n] = B[k*Nc + n]   (NN, row-major B)
//   TRANSB=true : B'[k][n] = B[n*K  + k]   (NT, e.g. H^T)
// Tiles: 128x128x8, 256 threads, 8x8 per thread (4+4 split strips).
// Requires M,Nc multiples of 128 and K multiple of 8 (holds here).
// ---------------------------------------------------------------------------
template <bool TRANSB, bool ADDC>
__global__ void __launch_bounds__(256)
gemm_kernel(const float* __restrict__ Ag, const float* __restrict__ Bg,
            const float* __restrict__ Cadd, float* __restrict__ Cg,
            float* __restrict__ C2, int M, int Nc, int K) {
    __shared__ float As[8][128];
    __shared__ float Bs[8][128];
    const int tid = threadIdx.x;
    const int bm = blockIdx.y * 128;
    const int bn = blockIdx.x * 128;
    const int ty = tid >> 4;     // 0..15
    const int tx = tid & 15;     // 0..15

    float acc[8][8];
    #pragma unroll
    for (int i = 0; i < 8; i++)
        #pragma unroll
        for (int j = 0; j < 8; j++) acc[i][j] = 0.f;

    const int arow = tid >> 1;          // 0..127
    const int acol = (tid & 1) * 4;     // 0 or 4
    const int brow = tid >> 5;          // 0..7
    const int bcol = (tid & 31) * 4;    // 0..124

    for (int k0 = 0; k0 < K; k0 += 8) {
        float4 av = *(const float4*)(Ag + (size_t)(bm + arow) * K + k0 + acol);
        As[acol + 0][arow] = av.x;
        As[acol + 1][arow] = av.y;
        As[acol + 2][arow] = av.z;
        As[acol + 3][arow] = av.w;
        if (!TRANSB) {
            float4 bv = *(const float4*)(Bg + (size_t)(k0 + brow) * Nc + bn + bcol);
            *(float4*)&Bs[brow][bcol] = bv;
        } else {
            float4 bv = *(const float4*)(Bg + (size_t)(bn + arow) * K + k0 + acol);
            Bs[acol + 0][arow] = bv.x;
            Bs[acol + 1][arow] = bv.y;
            Bs[acol + 2][arow] = bv.z;
            Bs[acol + 3][arow] = bv.w;
        }
        __syncthreads();
        #pragma unroll
        for (int kk = 0; kk < 8; kk++) {
            float a[8], b[8];
            *(float4*)&a[0] = *(const float4*)&As[kk][ty * 4];
            *(float4*)&a[4] = *(const float4*)&As[kk][64 + ty * 4];
            *(float4*)&b[0] = *(const float4*)&Bs[kk][tx * 4];
            *(float4*)&b[4] = *(const float4*)&Bs[kk][64 + tx * 4];
            #pragma unroll
            for (int i = 0; i < 8; i++)
                #pragma unroll
                for (int j = 0; j < 8; j++)
                    acc[i][j] += a[i] * b[j];
        }
        __syncthreads();
    }

    #pragma unroll
    for (int i = 0; i < 8; i++) {
        const int row = bm + ((i < 4) ? (ty * 4 + i) : (64 + ty * 4 + (i - 4)));
        #pragma unroll
        for (int jh = 0; jh < 2; jh++) {
            const int col = bn + ((jh == 0) ? (tx * 4) : (64 + tx * 4));
            float4 v;
            v.x = acc[i][jh * 4 + 0];
            v.y = acc[i][jh * 4 + 1];
            v.z = acc[i][jh * 4 + 2];
            v.w = acc[i][jh * 4 + 3];
            if (ADDC) {
                float4 cv = *(const float4*)(Cadd + (size_t)row * Nc + col);
                v.x += cv.x; v.y += cv.y; v.z += cv.z; v.w += cv.w;
            }
            *(float4*)(Cg + (size_t)row * Nc + col) = v;
            if (C2) *(float4*)(C2 + (size_t)row * Nc + col) = v;
        }
    }
}

// ---------------------------------------------------------------------------
// Launch sequence.
//   out layout: [s_final (BSZ*ND)] [traj (26*BSZ*ND)]
//   traj[0] = 0;  traj[t+1] = s_t @ W + c ;  s_final = traj[25]
// ---------------------------------------------------------------------------
extern "C" void kernel_launch(void* const* d_in, const int* in_sizes, int n_in,
                              void* d_out, int out_size) {
    const float* A  = (const float*)d_in[0];
    const float* H  = (const float*)d_in[1];
    const float* y  = (const float*)d_in[2];
    const float* iw = (const float*)d_in[3];

    float* out     = (float*)d_out;
    float* s_final = out;
    float* traj    = out + (size_t)BSZ * ND;

    float *invM, *Tm, *W, *yMF, *c, *s0;
    cudaGetSymbolAddress((void**)&invM, g_invM);
    cudaGetSymbolAddress((void**)&Tm,   g_T);
    cudaGetSymbolAddress((void**)&W,    g_W);
    cudaGetSymbolAddress((void**)&yMF,  g_yMF);
    cudaGetSymbolAddress((void**)&c,    g_c);
    cudaGetSymbolAddress((void**)&s0,   g_s0);

    // Precompute: invM, T, yMF = y @ H^T
    trinv_kernel<<<ND / 4, 128>>>(A, iw, invM);
    build_T_kernel<<<ND, 256>>>(A, iw);
    gemm_kernel<true, false><<<dim3(ND / 128, BSZ / 128), 256>>>(
        y, H, nullptr, yMF, nullptr, BSZ, ND, ND);

    // W = T @ invM ; c = yMF @ invM
    gemm_kernel<false, false><<<dim3(ND / 128, ND / 128), 256>>>(
        Tm, invM, nullptr, W, nullptr, ND, ND, ND);
    gemm_kernel<false, false><<<dim3(ND / 128, BSZ / 128), 256>>>(
        yMF, invM, nullptr, c, nullptr, BSZ, ND, ND);

    // s0 = yMF / d ; traj[0] = 0
    s0_kernel<<<(BSZ * ND) / 256, 256>>>(A);
    zero_kernel<<<(BSZ * ND / 4) / 256, 256>>>((float4*)traj);

    // Main loop: traj[t+1] = s_t @ W + c ; last iteration also writes s_final
    const float* s = s0;
    for (int t = 0; t < ITERS; t++) {
        float* outp = traj + (size_t)(t + 1) * BSZ * ND;
        float* dual = (t == ITERS - 1) ? s_final : nullptr;
        gemm_kernel<false, true><<<dim3(ND / 128, BSZ / 128), 256>>>(
            s, W, c, outp, dual, BSZ, ND, ND);
        s = outp;
    }
}

// round 7
// speedup vs baseline: 2.9630x; 2.9630x over previous
#include <cuda_runtime.h>
#include <cuda_bf16.h>
#include <cstdint>

// ---------------------------------------------------------------------------
// Problem constants
// ---------------------------------------------------------------------------
constexpr int ND    = 1024;
constexpr int BSZ   = 2048;
constexpr int ITERS = 25;
constexpr int KD    = 1024;

// ---------------------------------------------------------------------------
// Helpers (baseline PTX only — NO sm_103a-only features)
// ---------------------------------------------------------------------------
__device__ __forceinline__ uint32_t smem_to_u32(const void* p) {
    uint32_t a;
    asm("{ .reg .u64 t; cvta.to.shared.u64 t, %1; cvt.u32.u64 %0, t; }"
        : "=r"(a) : "l"(p));
    return a;
}
__device__ __forceinline__ void cp_async16(uint32_t sa, const void* g) {
    asm volatile("cp.async.cg.shared.global [%0], [%1], 16;" :: "r"(sa), "l"(g));
}
__device__ __forceinline__ void cp_async_commit() {
    asm volatile("cp.async.commit_group;" ::: "memory");
}
__device__ __forceinline__ void cp_async_wait1() {
    asm volatile("cp.async.wait_group 1;" ::: "memory");
}
__device__ __forceinline__ void ldsm_x4(uint32_t& r0, uint32_t& r1, uint32_t& r2,
                                        uint32_t& r3, uint32_t addr) {
    asm volatile("ldmatrix.sync.aligned.m8n8.x4.shared.b16 {%0,%1,%2,%3}, [%4];"
                 : "=r"(r0), "=r"(r1), "=r"(r2), "=r"(r3) : "r"(addr));
}
__device__ __forceinline__ void mma16816(float* d, const uint32_t* a, const uint32_t* b) {
    asm volatile(
        "mma.sync.aligned.m16n8k16.row.col.f32.bf16.bf16.f32 "
        "{%0,%1,%2,%3},{%4,%5,%6,%7},{%8,%9},{%0,%1,%2,%3};"
        : "+f"(d[0]), "+f"(d[1]), "+f"(d[2]), "+f"(d[3])
        : "r"(a[0]), "r"(a[1]), "r"(a[2]), "r"(a[3]), "r"(b[0]), "r"(b[1]));
}

// ---------------------------------------------------------------------------
// Scratch (device globals)
// ---------------------------------------------------------------------------
__device__ float g_invM[ND * ND];
__device__ float g_yMF [BSZ * ND];
__device__ float g_c   [BSZ * ND];                 // row-major c[m][n]
__device__ __nv_bfloat16 g_invMt_hi[ND * ND],  g_invMt_lo[ND * ND];
__device__ __nv_bfloat16 g_T_hi    [ND * ND],  g_T_lo    [ND * ND];
__device__ __nv_bfloat16 g_H_hi    [ND * ND],  g_H_lo    [ND * ND];
__device__ __nv_bfloat16 g_V_hi    [ND * ND],  g_V_lo    [ND * ND];
__device__ __nv_bfloat16 g_y_hi    [BSZ * ND], g_y_lo    [BSZ * ND];
__device__ __nv_bfloat16 g_yMF_hi  [BSZ * ND], g_yMF_lo  [BSZ * ND];
__device__ __nv_bfloat16 g_sA_hi   [BSZ * ND], g_sA_lo   [BSZ * ND];
__device__ __nv_bfloat16 g_sB_hi   [BSZ * ND], g_sB_lo   [BSZ * ND];

// ---------------------------------------------------------------------------
// Small kernels
// ---------------------------------------------------------------------------
__global__ void trinv_kernel(const float* __restrict__ A,
                             const float* __restrict__ iwp,
                             float* __restrict__ invM) {
    __shared__ float xs[4][ND];
    const int warp = threadIdx.x >> 5;
    const int lane = threadIdx.x & 31;
    const int j = blockIdx.x * 4 + warp;
    const float iw = *iwp;
    float* x = xs[warp];
    if (lane == 0) x[j] = 1.0f / (iw * A[(size_t)j * ND + j]);
    __syncwarp();
    for (int i = j + 1; i < ND; i++) {
        const float* Ai = A + (size_t)i * ND;
        float sum = 0.f;
        for (int k = j + lane; k < i; k += 32) sum += Ai[k] * x[k];
        #pragma unroll
        for (int o = 16; o > 0; o >>= 1) sum += __shfl_xor_sync(0xffffffffu, sum, o);
        if (lane == 0) x[i] = -sum / (iw * Ai[i]);
        __syncwarp();
    }
    for (int i = lane; i < ND; i += 32)
        invM[(size_t)i * ND + j] = (i < j) ? 0.f : x[i];
}

__device__ __forceinline__ void split_store(float v, __nv_bfloat16* hi, __nv_bfloat16* lo,
                                            size_t idx) {
    __nv_bfloat16 h = __float2bfloat16(v);
    hi[idx] = h;
    lo[idx] = __float2bfloat16(v - __bfloat162float(h));
}

__global__ void split_kernel(const float* __restrict__ src,
                             __nv_bfloat16* __restrict__ hi,
                             __nv_bfloat16* __restrict__ lo) {
    size_t i = (size_t)blockIdx.x * blockDim.x + threadIdx.x;
    split_store(src[i], hi, lo, i);
}

__global__ void build_T_split(const float* __restrict__ A, const float* __restrict__ iwp) {
    const int k = blockIdx.x;
    const float iw = *iwp;
    for (int j = threadIdx.x; j < ND; j += blockDim.x) {
        float v = 0.f;
        if (j == k)      v = (iw - 1.f) * A[(size_t)k * ND + k];
        else if (j > k)  v = -A[(size_t)k * ND + j];
        split_store(v, g_T_hi, g_T_lo, (size_t)k * ND + j);
    }
}

__global__ void invMt_split(const float* __restrict__ invM) {
    size_t o = (size_t)blockIdx.x * blockDim.x + threadIdx.x;
    int k = (int)(o & (ND - 1));
    int n = (int)(o >> 10);
    split_store(invM[(size_t)k * ND + n], g_invMt_hi, g_invMt_lo, o);
}

__global__ void s0_split(const float* __restrict__ A) {
    size_t i = (size_t)blockIdx.x * blockDim.x + threadIdx.x;
    int col = (int)(i & (ND - 1));
    float v = g_yMF[i] / A[(size_t)col * ND + col];
    split_store(v, g_sA_hi, g_sA_lo, i);
}

__global__ void zero_kernel(float4* __restrict__ p) {
    size_t i = (size_t)blockIdx.x * blockDim.x + threadIdx.x;
    p[i] = make_float4(0.f, 0.f, 0.f, 0.f);
}

// ---------------------------------------------------------------------------
// mma.sync split-bf16 GEMM: D[m,n] = sum_k (Ahi+Alo)[m,k]*(Bhi+Blo)[n,k]
//   (3 terms: hi*hi + hi*lo + lo*hi; fp32 accumulate)
// Block tile 128x128, 256 threads = 8 warps (4x2), warp tile 32x64.
// K chunks of 32; 3-stage cp.async pipeline. Smem rows: 64B data + 16B pad
// (stride 5 x 16B, coprime with 8 -> conflict-free ldmatrix).
// Epilogue: +cAdd, fp32 store (1-2 dests), bf16 hi/lo re-split; all stores
// coalesced via per-warp 32x33 smem transpose.
// ---------------------------------------------------------------------------
constexpr int CHUNK   = 32;
constexpr int NC      = KD / CHUNK;          // 32
constexpr int ROWB    = 80;                  // 64B data + 16B pad
constexpr int TILE_SM = 128 * ROWB;          // 10240 B
constexpr int STAGE_SM = 4 * TILE_SM;        // 40960 B (Ahi,Alo,Bhi,Blo)
constexpr int NSTAGE  = 3;
constexpr int GEMM_SMEM = NSTAGE * STAGE_SM; // 122880 B

__global__ void __launch_bounds__(256)
gemm_mma(const __nv_bfloat16* __restrict__ Ahi, const __nv_bfloat16* __restrict__ Alo,
         const __nv_bfloat16* __restrict__ Bhi, const __nv_bfloat16* __restrict__ Blo,
         const float* __restrict__ cAdd,
         float* __restrict__ outRow, float* __restrict__ outDual,
         __nv_bfloat16* __restrict__ outHi, __nv_bfloat16* __restrict__ outLo) {
    extern __shared__ char smem[];
    const uint32_t sb = smem_to_u32(smem);
    const int tid  = threadIdx.x;
    const int lane = tid & 31;
    const int w    = tid >> 5;          // 0..7
    const int wm   = w >> 1;            // 0..3
    const int wn   = w & 1;             // 0..1
    const int bm = blockIdx.y * 128;
    const int bn = blockIdx.x * 128;
    const int mo = wm * 32;             // warp row offset in tile
    const int no = wn * 64;             // warp col offset in tile

    // ---- global load addressing: thread -> (row = tid>>1, two 16B groups) ----
    const int grow = tid >> 1;
    const int g0   = (tid & 1) * 2;     // 16B group 0 or 2
    const char* gsrc[4] = {
        (const char*)(Ahi + (size_t)(bm + grow) * KD),
        (const char*)(Alo + (size_t)(bm + grow) * KD),
        (const char*)(Bhi + (size_t)(bn + grow) * KD),
        (const char*)(Blo + (size_t)(bn + grow) * KD) };
    const uint32_t sdst = grow * ROWB + g0 * 16;

    // ---- accumulators ----
    float acc[2][8][4];
    #pragma unroll
    for (int i = 0; i < 2; i++)
        #pragma unroll
        for (int j = 0; j < 8; j++)
            #pragma unroll
            for (int q = 0; q < 4; q++) acc[i][j][q] = 0.f;

    // ---- lane-constant ldmatrix offsets ----
    const int lt = lane >> 3, lr = lane & 7;
    // A tiles: t0=(m0-7,kg0) t1=(m8-15,kg0) t2=(m0-7,kg1) t3=(m8-15,kg1)
    const uint32_t aoff = (uint32_t)(((lt & 1) * 8 + lr) * ROWB + (lt >> 1) * 16);
    // B tiles: t0=(n0-7,kg0) t1=(n0-7,kg1) t2=(n8-15,kg0) t3=(n8-15,kg1)
    const uint32_t boff = (uint32_t)(((lt >> 1) * 8 + lr) * ROWB + (lt & 1) * 16);

    auto load_stage = [&](int s, int k0) {
        const uint32_t stage = sb + s * STAGE_SM;
        #pragma unroll
        for (int t = 0; t < 4; t++) {
            const char* g = gsrc[t] + (size_t)(k0 + g0 * 8) * 2;  // bf16 -> bytes
            const uint32_t d = stage + t * TILE_SM + sdst;
            cp_async16(d, g);
            cp_async16(d + 16, g + 16);
        }
    };

    // prologue: stages 0,1
    load_stage(0, 0);  cp_async_commit();
    load_stage(1, CHUNK); cp_async_commit();

    for (int i = 0; i < NC; i++) {
        cp_async_wait1();      // stage i complete
        __syncthreads();       // (also: all warps done with stage i-1)

        const uint32_t stage = sb + (i % NSTAGE) * STAGE_SM;
        const uint32_t At_hi = stage + 0 * TILE_SM + mo * ROWB;
        const uint32_t At_lo = stage + 1 * TILE_SM + mo * ROWB;
        const uint32_t Bt_hi = stage + 2 * TILE_SM + no * ROWB;
        const uint32_t Bt_lo = stage + 3 * TILE_SM + no * ROWB;

        #pragma unroll
        for (int g2 = 0; g2 < 2; g2++) {       // two k16 steps per chunk
            uint32_t ah[2][4], al[2][4];
            #pragma unroll
            for (int mt = 0; mt < 2; mt++) {
                const uint32_t o = mt * 16 * ROWB + g2 * 32 + aoff;
                ldsm_x4(ah[mt][0], ah[mt][1], ah[mt][2], ah[mt][3], At_hi + o);
                ldsm_x4(al[mt][0], al[mt][1], al[mt][2], al[mt][3], At_lo + o);
            }
            #pragma unroll
            for (int np = 0; np < 4; np++) {   // n-pairs of 16
                uint32_t bh[4], bl[4];
                const uint32_t o = np * 16 * ROWB + g2 * 32 + boff;
                ldsm_x4(bh[0], bh[1], bh[2], bh[3], Bt_hi + o);
                ldsm_x4(bl[0], bl[1], bl[2], bl[3], Bt_lo + o);
                #pragma unroll
                for (int mt = 0; mt < 2; mt++) {
                    #pragma unroll
                    for (int nt2 = 0; nt2 < 2; nt2++) {
                        float* d = acc[mt][np * 2 + nt2];
                        mma16816(d, ah[mt], &bh[nt2 * 2]);
                        mma16816(d, ah[mt], &bl[nt2 * 2]);
                        mma16816(d, al[mt], &bh[nt2 * 2]);
                    }
                }
            }
        }

        // tail: load stage i+2 (or commit an empty group to keep counts exact)
        if (i + 2 < NC) load_stage((i + 2) % NSTAGE, (i + 2) * CHUNK);
        cp_async_commit();
    }
    __syncthreads();   // all compute done; smem free for epilogue reuse

    // ---- epilogue: per-warp 32x33 transpose buffer in smem ----
    float* buf = (float*)smem + w * (32 * 33);
    #pragma unroll
    for (int h = 0; h < 2; h++) {              // two 32-col halves of warp tile
        #pragma unroll
        for (int mt = 0; mt < 2; mt++) {
            #pragma unroll
            for (int nt = 0; nt < 4; nt++) {
                const float* d = acc[mt][h * 4 + nt];
                const int r = mt * 16 + (lane >> 2);
                const int c = nt * 8 + (lane & 3) * 2;
                buf[r * 33 + c]           = d[0];
                buf[r * 33 + c + 1]       = d[1];
                buf[(r + 8) * 33 + c]     = d[2];
                buf[(r + 8) * 33 + c + 1] = d[3];
            }
        }
        __syncwarp();
        const int gc = bn + no + h * 32 + lane;
        #pragma unroll
        for (int rr = 0; rr < 32; rr++) {
            float v = buf[rr * 33 + lane];
            const size_t idx = (size_t)(bm + mo + rr) * ND + gc;
            if (cAdd) v += cAdd[idx];
            if (outRow)  outRow[idx]  = v;
            if (outDual) outDual[idx] = v;
            if (outHi) {
                __nv_bfloat16 hh = __float2bfloat16(v);
                outHi[idx] = hh;
                outLo[idx] = __float2bfloat16(v - __bfloat162float(hh));
            }
        }
        __syncwarp();
    }
}

// ---------------------------------------------------------------------------
// Launch sequence
// ---------------------------------------------------------------------------
extern "C" void kernel_launch(void* const* d_in, const int* in_sizes, int n_in,
                              void* d_out, int out_size) {
    const float* A  = (const float*)d_in[0];
    const float* H  = (const float*)d_in[1];
    const float* y  = (const float*)d_in[2];
    const float* iw = (const float*)d_in[3];

    float* out     = (float*)d_out;
    float* s_final = out;
    float* traj    = out + (size_t)BSZ * ND;

    cudaFuncSetAttribute(gemm_mma, cudaFuncAttributeMaxDynamicSharedMemorySize, GEMM_SMEM);

    float *invM, *yMF, *c;
    __nv_bfloat16 *invMt_hi, *invMt_lo, *T_hi, *T_lo, *H_hi, *H_lo, *V_hi, *V_lo;
    __nv_bfloat16 *y_hi, *y_lo, *yMF_hi, *yMF_lo, *sA_hi, *sA_lo, *sB_hi, *sB_lo;
    cudaGetSymbolAddress((void**)&invM,     g_invM);
    cudaGetSymbolAddress((void**)&yMF,      g_yMF);
    cudaGetSymbolAddress((void**)&c,        g_c);
    cudaGetSymbolAddress((void**)&invMt_hi, g_invMt_hi);
    cudaGetSymbolAddress((void**)&invMt_lo, g_invMt_lo);
    cudaGetSymbolAddress((void**)&T_hi,     g_T_hi);
    cudaGetSymbolAddress((void**)&T_lo,     g_T_lo);
    cudaGetSymbolAddress((void**)&H_hi,     g_H_hi);
    cudaGetSymbolAddress((void**)&H_lo,     g_H_lo);
    cudaGetSymbolAddress((void**)&V_hi,     g_V_hi);
    cudaGetSymbolAddress((void**)&V_lo,     g_V_lo);
    cudaGetSymbolAddress((void**)&y_hi,     g_y_hi);
    cudaGetSymbolAddress((void**)&y_lo,     g_y_lo);
    cudaGetSymbolAddress((void**)&yMF_hi,   g_yMF_hi);
    cudaGetSymbolAddress((void**)&yMF_lo,   g_yMF_lo);
    cudaGetSymbolAddress((void**)&sA_hi,    g_sA_hi);
    cudaGetSymbolAddress((void**)&sA_lo,    g_sA_lo);
    cudaGetSymbolAddress((void**)&sB_hi,    g_sB_hi);
    cudaGetSymbolAddress((void**)&sB_lo,    g_sB_lo);

    // Precompute
    trinv_kernel<<<ND / 4, 128>>>(A, iw, invM);
    invMt_split<<<(ND * ND) / 256, 256>>>(invM);
    build_T_split<<<ND, 256>>>(A, iw);
    split_kernel<<<(ND * ND) / 256, 256>>>(H, H_hi, H_lo);
    split_kernel<<<(BSZ * ND) / 256, 256>>>(y, y_hi, y_lo);

    const dim3 gridB(ND / 128, BSZ / 128);   // batch-sized GEMMs
    const dim3 gridS(ND / 128, ND / 128);    // square GEMMs

    // yMF = y @ H^T  (fp32 + splits)
    gemm_mma<<<gridB, 256, GEMM_SMEM>>>(
        y_hi, y_lo, H_hi, H_lo, nullptr, yMF, nullptr, yMF_hi, yMF_lo);

    // c = yMF @ invM  (row-major fp32):  c[m][n] = sum_k yMF[m][k] invMt[n][k]
    gemm_mma<<<gridB, 256, GEMM_SMEM>>>(
        yMF_hi, yMF_lo, invMt_hi, invMt_lo, nullptr, c, nullptr, nullptr, nullptr);

    // V[n][k] = W[k][n] = sum_j invMt[n][j] * T[k][j]  (splits only)
    gemm_mma<<<gridS, 256, GEMM_SMEM>>>(
        invMt_hi, invMt_lo, T_hi, T_lo, nullptr, nullptr, nullptr, V_hi, V_lo);

    // s0 = yMF / d -> sA splits ; traj[0] = 0
    s0_split<<<(BSZ * ND) / 256, 256>>>(A);
    zero_kernel<<<(BSZ * ND / 4) / 256, 256>>>((float4*)traj);

    // Main loop: traj[t+1] = s_t @ W + c ; epilogue re-splits next s
    __nv_bfloat16 *srcHi = sA_hi, *srcLo = sA_lo, *dstHi = sB_hi, *dstLo = sB_lo;
    for (int t = 0; t < ITERS; t++) {
        float* outp = traj + (size_t)(t + 1) * BSZ * ND;
        float* dual = (t == ITERS - 1) ? s_final : nullptr;
        gemm_mma<<<gridB, 256, GEMM_SMEM>>>(
            srcHi, srcLo, V_hi, V_lo, c, outp, dual, dstHi, dstLo);
        __nv_bfloat16* th = srcHi; srcHi = dstHi; dstHi = th;
        __nv_bfloat16* tl = srcLo; srcLo = dstLo; dstLo = tl;
    }
}

// round 8
// speedup vs baseline: 2.9826x; 1.0066x over previous
#include <cuda_runtime.h>
#include <cuda_bf16.h>
#include <cstdint>

// ---------------------------------------------------------------------------
// Problem constants
// ---------------------------------------------------------------------------
constexpr int ND    = 1024;
constexpr int BSZ   = 2048;
constexpr int ITERS = 25;
constexpr int KD    = 1024;

// ---------------------------------------------------------------------------
// Helpers (baseline PTX only — NO sm_103a-only features)
// ---------------------------------------------------------------------------
__device__ __forceinline__ uint32_t smem_to_u32(const void* p) {
    uint32_t a;
    asm("{ .reg .u64 t; cvta.to.shared.u64 t, %1; cvt.u32.u64 %0, t; }"
        : "=r"(a) : "l"(p));
    return a;
}
__device__ __forceinline__ void cp_async16(uint32_t sa, const void* g) {
    asm volatile("cp.async.cg.shared.global [%0], [%1], 16;" :: "r"(sa), "l"(g));
}
__device__ __forceinline__ void cp_async_commit() {
    asm volatile("cp.async.commit_group;" ::: "memory");
}
__device__ __forceinline__ void cp_async_wait1() {
    asm volatile("cp.async.wait_group 1;" ::: "memory");
}
__device__ __forceinline__ void ldsm_x4(uint32_t& r0, uint32_t& r1, uint32_t& r2,
                                        uint32_t& r3, uint32_t addr) {
    asm volatile("ldmatrix.sync.aligned.m8n8.x4.shared.b16 {%0,%1,%2,%3}, [%4];"
                 : "=r"(r0), "=r"(r1), "=r"(r2), "=r"(r3) : "r"(addr));
}
__device__ __forceinline__ void mma16816(float* d, const uint32_t* a, const uint32_t* b) {
    asm volatile(
        "mma.sync.aligned.m16n8k16.row.col.f32.bf16.bf16.f32 "
        "{%0,%1,%2,%3},{%4,%5,%6,%7},{%8,%9},{%0,%1,%2,%3};"
        : "+f"(d[0]), "+f"(d[1]), "+f"(d[2]), "+f"(d[3])
        : "r"(a[0]), "r"(a[1]), "r"(a[2]), "r"(a[3]), "r"(b[0]), "r"(b[1]));
}

// ---------------------------------------------------------------------------
// Scratch (device globals)
// ---------------------------------------------------------------------------
__device__ float g_invM[ND * ND];
__device__ float g_yMF [BSZ * ND];
__device__ float g_c   [BSZ * ND];                 // row-major c[m][n]
__device__ __nv_bfloat16 g_invMt_hi[ND * ND],  g_invMt_lo[ND * ND];
__device__ __nv_bfloat16 g_T_hi    [ND * ND],  g_T_lo    [ND * ND];
__device__ __nv_bfloat16 g_H_hi    [ND * ND],  g_H_lo    [ND * ND];
__device__ __nv_bfloat16 g_V_hi    [ND * ND],  g_V_lo    [ND * ND];
__device__ __nv_bfloat16 g_y_hi    [BSZ * ND], g_y_lo    [BSZ * ND];
__device__ __nv_bfloat16 g_yMF_hi  [BSZ * ND], g_yMF_lo  [BSZ * ND];
__device__ __nv_bfloat16 g_sA_hi   [BSZ * ND], g_sA_lo   [BSZ * ND];
__device__ __nv_bfloat16 g_sB_hi   [BSZ * ND], g_sB_lo   [BSZ * ND];

// ---------------------------------------------------------------------------
// Small kernels
// ---------------------------------------------------------------------------
__global__ void trinv_kernel(const float* __restrict__ A,
                             const float* __restrict__ iwp,
                             float* __restrict__ invM) {
    __shared__ float xs[4][ND];
    const int warp = threadIdx.x >> 5;
    const int lane = threadIdx.x & 31;
    const int j = blockIdx.x * 4 + warp;
    const float iw = *iwp;
    float* x = xs[warp];
    if (lane == 0) x[j] = 1.0f / (iw * A[(size_t)j * ND + j]);
    __syncwarp();
    for (int i = j + 1; i < ND; i++) {
        const float* Ai = A + (size_t)i * ND;
        float sum = 0.f;
        for (int k = j + lane; k < i; k += 32) sum += Ai[k] * x[k];
        #pragma unroll
        for (int o = 16; o > 0; o >>= 1) sum += __shfl_xor_sync(0xffffffffu, sum, o);
        if (lane == 0) x[i] = -sum / (iw * Ai[i]);
        __syncwarp();
    }
    for (int i = lane; i < ND; i += 32)
        invM[(size_t)i * ND + j] = (i < j) ? 0.f : x[i];
}

__device__ __forceinline__ void split_store(float v, __nv_bfloat16* hi, __nv_bfloat16* lo,
                                            size_t idx) {
    __nv_bfloat16 h = __float2bfloat16(v);
    hi[idx] = h;
    lo[idx] = __float2bfloat16(v - __bfloat162float(h));
}

__global__ void split_kernel(const float* __restrict__ src,
                             __nv_bfloat16* __restrict__ hi,
                             __nv_bfloat16* __restrict__ lo) {
    size_t i = (size_t)blockIdx.x * blockDim.x + threadIdx.x;
    split_store(src[i], hi, lo, i);
}

__global__ void build_T_split(const float* __restrict__ A, const float* __restrict__ iwp) {
    const int k = blockIdx.x;
    const float iw = *iwp;
    for (int j = threadIdx.x; j < ND; j += blockDim.x) {
        float v = 0.f;
        if (j == k)      v = (iw - 1.f) * A[(size_t)k * ND + k];
        else if (j > k)  v = -A[(size_t)k * ND + j];
        split_store(v, g_T_hi, g_T_lo, (size_t)k * ND + j);
    }
}

__global__ void invMt_split(const float* __restrict__ invM) {
    size_t o = (size_t)blockIdx.x * blockDim.x + threadIdx.x;
    int k = (int)(o & (ND - 1));
    int n = (int)(o >> 10);
    split_store(invM[(size_t)k * ND + n], g_invMt_hi, g_invMt_lo, o);
}

__global__ void s0_split(const float* __restrict__ A) {
    size_t i = (size_t)blockIdx.x * blockDim.x + threadIdx.x;
    int col = (int)(i & (ND - 1));
    float v = g_yMF[i] / A[(size_t)col * ND + col];
    split_store(v, g_sA_hi, g_sA_lo, i);
}

__global__ void zero_kernel(float4* __restrict__ p) {
    size_t i = (size_t)blockIdx.x * blockDim.x + threadIdx.x;
    p[i] = make_float4(0.f, 0.f, 0.f, 0.f);
}

// ---------------------------------------------------------------------------
// mma.sync split-bf16 GEMM: D[m,n] = sum_k (Ahi+Alo)[m,k]*(Bhi+Blo)[n,k]
//   3 terms (hh + hl + lh), fp32 accumulate.
// Block tile 128x128, 256 threads = 8 warps (4x2), warp tile 32x64.
// K chunks of 32; 3-stage cp.async pipeline.
// KEY CHANGE vs R7: per k16 step, ALL A and B fragments are loaded into
// registers first, then the 48 MMAs are issued in 3 passes of 16 INDEPENDENT
// MMAs (term-major order) — accumulator reuse distance 16 instead of 1,
// eliminating the HMMA RAW-chain stalls.
// ---------------------------------------------------------------------------
constexpr int CHUNK   = 32;
constexpr int NC      = KD / CHUNK;          // 32
constexpr int ROWB    = 80;                  // 64B data + 16B pad
constexpr int TILE_SM = 128 * ROWB;          // 10240 B
constexpr int STAGE_SM = 4 * TILE_SM;        // 40960 B (Ahi,Alo,Bhi,Blo)
constexpr int NSTAGE  = 3;
constexpr int GEMM_SMEM = NSTAGE * STAGE_SM; // 122880 B

__global__ void __launch_bounds__(256)
gemm_mma(const __nv_bfloat16* __restrict__ Ahi, const __nv_bfloat16* __restrict__ Alo,
         const __nv_bfloat16* __restrict__ Bhi, const __nv_bfloat16* __restrict__ Blo,
         const float* __restrict__ cAdd,
         float* __restrict__ outRow, float* __restrict__ outDual,
         __nv_bfloat16* __restrict__ outHi, __nv_bfloat16* __restrict__ outLo) {
    extern __shared__ char smem[];
    const uint32_t sb = smem_to_u32(smem);
    const int tid  = threadIdx.x;
    const int lane = tid & 31;
    const int w    = tid >> 5;          // 0..7
    const int wm   = w >> 1;            // 0..3
    const int wn   = w & 1;             // 0..1
    const int bm = blockIdx.y * 128;
    const int bn = blockIdx.x * 128;
    const int mo = wm * 32;             // warp row offset in tile
    const int no = wn * 64;             // warp col offset in tile

    // ---- global load addressing ----
    const int grow = tid >> 1;
    const int g0   = (tid & 1) * 2;     // 16B group 0 or 2
    const char* gsrc[4] = {
        (const char*)(Ahi + (size_t)(bm + grow) * KD),
        (const char*)(Alo + (size_t)(bm + grow) * KD),
        (const char*)(Bhi + (size_t)(bn + grow) * KD),
        (const char*)(Blo + (size_t)(bn + grow) * KD) };
    const uint32_t sdst = grow * ROWB + g0 * 16;

    // ---- accumulators ----
    float acc[2][8][4];
    #pragma unroll
    for (int i = 0; i < 2; i++)
        #pragma unroll
        for (int j = 0; j < 8; j++)
            #pragma unroll
            for (int q = 0; q < 4; q++) acc[i][j][q] = 0.f;

    // ---- lane-constant ldmatrix offsets ----
    const int lt = lane >> 3, lr = lane & 7;
    const uint32_t aoff = (uint32_t)(((lt & 1) * 8 + lr) * ROWB + (lt >> 1) * 16);
    const uint32_t boff = (uint32_t)(((lt >> 1) * 8 + lr) * ROWB + (lt & 1) * 16);

    auto load_stage = [&](int s, int k0) {
        const uint32_t stage = sb + s * STAGE_SM;
        #pragma unroll
        for (int t = 0; t < 4; t++) {
            const char* g = gsrc[t] + (size_t)(k0 + g0 * 8) * 2;
            const uint32_t d = stage + t * TILE_SM + sdst;
            cp_async16(d, g);
            cp_async16(d + 16, g + 16);
        }
    };

    // prologue: stages 0,1
    load_stage(0, 0);  cp_async_commit();
    load_stage(1, CHUNK); cp_async_commit();

    for (int i = 0; i < NC; i++) {
        cp_async_wait1();
        __syncthreads();

        const uint32_t stage = sb + (i % NSTAGE) * STAGE_SM;
        const uint32_t At_hi = stage + 0 * TILE_SM + mo * ROWB;
        const uint32_t At_lo = stage + 1 * TILE_SM + mo * ROWB;
        const uint32_t Bt_hi = stage + 2 * TILE_SM + no * ROWB;
        const uint32_t Bt_lo = stage + 3 * TILE_SM + no * ROWB;

        #pragma unroll
        for (int g2 = 0; g2 < 2; g2++) {       // two k16 steps per chunk
            // --- load ALL fragments for this k16 step ---
            uint32_t ah[2][4], al[2][4], bh[4][4], bl[4][4];
            #pragma unroll
            for (int mt = 0; mt < 2; mt++) {
                const uint32_t o = mt * 16 * ROWB + g2 * 32 + aoff;
                ldsm_x4(ah[mt][0], ah[mt][1], ah[mt][2], ah[mt][3], At_hi + o);
                ldsm_x4(al[mt][0], al[mt][1], al[mt][2], al[mt][3], At_lo + o);
            }
            #pragma unroll
            for (int np = 0; np < 4; np++) {
                const uint32_t o = np * 16 * ROWB + g2 * 32 + boff;
                ldsm_x4(bh[np][0], bh[np][1], bh[np][2], bh[np][3], Bt_hi + o);
                ldsm_x4(bl[np][0], bl[np][1], bl[np][2], bl[np][3], Bt_lo + o);
            }
            // --- pass 1: hi*hi (16 independent MMAs) ---
            #pragma unroll
            for (int np = 0; np < 4; np++)
                #pragma unroll
                for (int mt = 0; mt < 2; mt++)
                    #pragma unroll
                    for (int nt2 = 0; nt2 < 2; nt2++)
                        mma16816(acc[mt][np * 2 + nt2], ah[mt], &bh[np][nt2 * 2]);
            // --- pass 2: hi*lo ---
            #pragma unroll
            for (int np = 0; np < 4; np++)
                #pragma unroll
                for (int mt = 0; mt < 2; mt++)
                    #pragma unroll
                    for (int nt2 = 0; nt2 < 2; nt2++)
                        mma16816(acc[mt][np * 2 + nt2], ah[mt], &bl[np][nt2 * 2]);
            // --- pass 3: lo*hi ---
            #pragma unroll
            for (int np = 0; np < 4; np++)
                #pragma unroll
                for (int mt = 0; mt < 2; mt++)
                    #pragma unroll
                    for (int nt2 = 0; nt2 < 2; nt2++)
                        mma16816(acc[mt][np * 2 + nt2], al[mt], &bh[np][nt2 * 2]);
        }

        if (i + 2 < NC) load_stage((i + 2) % NSTAGE, (i + 2) * CHUNK);
        cp_async_commit();
    }
    __syncthreads();

    // ---- epilogue: per-warp 32x33 transpose buffer in smem ----
    float* buf = (float*)smem + w * (32 * 33);
    #pragma unroll
    for (int h = 0; h < 2; h++) {
        #pragma unroll
        for (int mt = 0; mt < 2; mt++) {
            #pragma unroll
            for (int nt = 0; nt < 4; nt++) {
                const float* d = acc[mt][h * 4 + nt];
                const int r = mt * 16 + (lane >> 2);
                const int c = nt * 8 + (lane & 3) * 2;
                buf[r * 33 + c]           = d[0];
                buf[r * 33 + c + 1]       = d[1];
                buf[(r + 8) * 33 + c]     = d[2];
                buf[(r + 8) * 33 + c + 1] = d[3];
            }
        }
        __syncwarp();
        const int gc = bn + no + h * 32 + lane;
        #pragma unroll
        for (int rr = 0; rr < 32; rr++) {
            float v = buf[rr * 33 + lane];
            const size_t idx = (size_t)(bm + mo + rr) * ND + gc;
            if (cAdd) v += cAdd[idx];
            if (outRow)  outRow[idx]  = v;
            if (outDual) outDual[idx] = v;
            if (outHi) {
                __nv_bfloat16 hh = __float2bfloat16(v);
                outHi[idx] = hh;
                outLo[idx] = __float2bfloat16(v - __bfloat162float(hh));
            }
        }
        __syncwarp();
    }
}

// ---------------------------------------------------------------------------
// Launch sequence
// ---------------------------------------------------------------------------
extern "C" void kernel_launch(void* const* d_in, const int* in_sizes, int n_in,
                              void* d_out, int out_size) {
    const float* A  = (const float*)d_in[0];
    const float* H  = (const float*)d_in[1];
    const float* y  = (const float*)d_in[2];
    const float* iw = (const float*)d_in[3];

    float* out     = (float*)d_out;
    float* s_final = out;
    float* traj    = out + (size_t)BSZ * ND;

    cudaFuncSetAttribute(gemm_mma, cudaFuncAttributeMaxDynamicSharedMemorySize, GEMM_SMEM);

    float *invM, *yMF, *c;
    __nv_bfloat16 *invMt_hi, *invMt_lo, *T_hi, *T_lo, *H_hi, *H_lo, *V_hi, *V_lo;
    __nv_bfloat16 *y_hi, *y_lo, *yMF_hi, *yMF_lo, *sA_hi, *sA_lo, *sB_hi, *sB_lo;
    cudaGetSymbolAddress((void**)&invM,     g_invM);
    cudaGetSymbolAddress((void**)&yMF,      g_yMF);
    cudaGetSymbolAddress((void**)&c,        g_c);
    cudaGetSymbolAddress((void**)&invMt_hi, g_invMt_hi);
    cudaGetSymbolAddress((void**)&invMt_lo, g_invMt_lo);
    cudaGetSymbolAddress((void**)&T_hi,     g_T_hi);
    cudaGetSymbolAddress((void**)&T_lo,     g_T_lo);
    cudaGetSymbolAddress((void**)&H_hi,     g_H_hi);
    cudaGetSymbolAddress((void**)&H_lo,     g_H_lo);
    cudaGetSymbolAddress((void**)&V_hi,     g_V_hi);
    cudaGetSymbolAddress((void**)&V_lo,     g_V_lo);
    cudaGetSymbolAddress((void**)&y_hi,     g_y_hi);
    cudaGetSymbolAddress((void**)&y_lo,     g_y_lo);
    cudaGetSymbolAddress((void**)&yMF_hi,   g_yMF_hi);
    cudaGetSymbolAddress((void**)&yMF_lo,   g_yMF_lo);
    cudaGetSymbolAddress((void**)&sA_hi,    g_sA_hi);
    cudaGetSymbolAddress((void**)&sA_lo,    g_sA_lo);
    cudaGetSymbolAddress((void**)&sB_hi,    g_sB_hi);
    cudaGetSymbolAddress((void**)&sB_lo,    g_sB_lo);

    // Precompute
    trinv_kernel<<<ND / 4, 128>>>(A, iw, invM);
    invMt_split<<<(ND * ND) / 256, 256>>>(invM);
    build_T_split<<<ND, 256>>>(A, iw);
    split_kernel<<<(ND * ND) / 256, 256>>>(H, H_hi, H_lo);
    split_kernel<<<(BSZ * ND) / 256, 256>>>(y, y_hi, y_lo);

    const dim3 gridB(ND / 128, BSZ / 128);   // batch-sized GEMMs
    const dim3 gridS(ND / 128, ND / 128);    // square GEMMs

    // yMF = y @ H^T  (fp32 + splits)
    gemm_mma<<<gridB, 256, GEMM_SMEM>>>(
        y_hi, y_lo, H_hi, H_lo, nullptr, yMF, nullptr, yMF_hi, yMF_lo);

    // c = yMF @ invM  (row-major fp32)
    gemm_mma<<<gridB, 256, GEMM_SMEM>>>(
        yMF_hi, yMF_lo, invMt_hi, invMt_lo, nullptr, c, nullptr, nullptr, nullptr);

    // V[n][k] = W[k][n] = sum_j invMt[n][j] * T[k][j]  (splits only)
    gemm_mma<<<gridS, 256, GEMM_SMEM>>>(
        invMt_hi, invMt_lo, T_hi, T_lo, nullptr, nullptr, nullptr, V_hi, V_lo);

    // s0 = yMF / d -> sA splits ; traj[0] = 0
    s0_split<<<(BSZ * ND) / 256, 256>>>(A);
    zero_kernel<<<(BSZ * ND / 4) / 256, 256>>>((float4*)traj);

    // Main loop: traj[t+1] = s_t @ W + c ; epilogue re-splits next s
    __nv_bfloat16 *srcHi = sA_hi, *srcLo = sA_lo, *dstHi = sB_hi, *dstLo = sB_lo;
    for (int t = 0; t < ITERS; t++) {
        float* outp = traj + (size_t)(t + 1) * BSZ * ND;
        float* dual = (t == ITERS - 1) ? s_final : nullptr;
        gemm_mma<<<gridB, 256, GEMM_SMEM>>>(
            srcHi, srcLo, V_hi, V_lo, c, outp, dual, dstHi, dstLo);
        __nv_bfloat16* th = srcHi; srcHi = dstHi; dstHi = th;
        __nv_bfloat16* tl = srcLo; srcLo = dstLo; dstLo = tl;
    }
}

// round 11
// speedup vs baseline: 3.1766x; 1.0651x over previous
#include <cuda_runtime.h>
#include <cuda_bf16.h>
#include <cstdint>

// ---------------------------------------------------------------------------
// Problem constants
// ---------------------------------------------------------------------------
constexpr int ND    = 1024;
constexpr int BSZ   = 2048;
constexpr int ITERS = 25;
constexpr int KD    = 1024;

// ---------------------------------------------------------------------------
// Helpers (baseline PTX only)
// ---------------------------------------------------------------------------
__device__ __forceinline__ uint32_t smem_to_u32(const void* p) {
    uint32_t a;
    asm("{ .reg .u64 t; cvta.to.shared.u64 t, %1; cvt.u32.u64 %0, t; }"
        : "=r"(a) : "l"(p));
    return a;
}
__device__ __forceinline__ void cp_async16(uint32_t sa, const void* g) {
    asm volatile("cp.async.cg.shared.global [%0], [%1], 16;" :: "r"(sa), "l"(g));
}
__device__ __forceinline__ void cp_async_commit() {
    asm volatile("cp.async.commit_group;" ::: "memory");
}
__device__ __forceinline__ void cp_async_wait1() {
    asm volatile("cp.async.wait_group 1;" ::: "memory");
}
__device__ __forceinline__ void ldsm_x4(uint32_t& r0, uint32_t& r1, uint32_t& r2,
                                        uint32_t& r3, uint32_t addr) {
    asm volatile("ldmatrix.sync.aligned.m8n8.x4.shared.b16 {%0,%1,%2,%3}, [%4];"
                 : "=r"(r0), "=r"(r1), "=r"(r2), "=r"(r3) : "r"(addr));
}
__device__ __forceinline__ void mma16816(float* d, const uint32_t* a, const uint32_t* b) {
    asm volatile(
        "mma.sync.aligned.m16n8k16.row.col.f32.bf16.bf16.f32 "
        "{%0,%1,%2,%3},{%4,%5,%6,%7},{%8,%9},{%0,%1,%2,%3};"
        : "+f"(d[0]), "+f"(d[1]), "+f"(d[2]), "+f"(d[3])
        : "r"(a[0]), "r"(a[1]), "r"(a[2]), "r"(a[3]), "r"(b[0]), "r"(b[1]));
}

// ---------------------------------------------------------------------------
// Scratch (device globals)
// ---------------------------------------------------------------------------
__device__ float g_invM[ND * ND];
__device__ float g_yMF [BSZ * ND];
__device__ float g_c   [BSZ * ND];
__device__ __nv_bfloat16 g_invMt_hi[ND * ND],  g_invMt_lo[ND * ND];
__device__ __nv_bfloat16 g_T_hi    [ND * ND],  g_T_lo    [ND * ND];
__device__ __nv_bfloat16 g_H_hi    [ND * ND],  g_H_lo    [ND * ND];
__device__ __nv_bfloat16 g_V_hi    [ND * ND],  g_V_lo    [ND * ND];
__device__ __nv_bfloat16 g_y_hi    [BSZ * ND], g_y_lo    [BSZ * ND];
__device__ __nv_bfloat16 g_yMF_hi  [BSZ * ND], g_yMF_lo  [BSZ * ND];
__device__ __nv_bfloat16 g_sA_hi   [BSZ * ND], g_sA_lo   [BSZ * ND];
__device__ __nv_bfloat16 g_sB_hi   [BSZ * ND], g_sB_lo   [BSZ * ND];

// ---------------------------------------------------------------------------
// trinv: column-parallel forward substitution for inv(iw*D + L)
// ---------------------------------------------------------------------------
__global__ void trinv_kernel(const float* __restrict__ A,
                             const float* __restrict__ iwp,
                             float* __restrict__ invM) {
    __shared__ float xs[4][ND];
    const int warp = threadIdx.x >> 5;
    const int lane = threadIdx.x & 31;
    const int j = blockIdx.x * 4 + warp;
    const float iw = *iwp;
    float* x = xs[warp];
    if (lane == 0) x[j] = 1.0f / (iw * A[(size_t)j * ND + j]);
    __syncwarp();
    for (int i = j + 1; i < ND; i++) {
        const float* Ai = A + (size_t)i * ND;
        float sum = 0.f;
        for (int k = j + lane; k < i; k += 32) sum += Ai[k] * x[k];
        #pragma unroll
        for (int o = 16; o > 0; o >>= 1) sum += __shfl_xor_sync(0xffffffffu, sum, o);
        if (lane == 0) x[i] = -sum / (iw * Ai[i]);
        __syncwarp();
    }
    for (int i = lane; i < ND; i += 32)
        invM[(size_t)i * ND + j] = (i < j) ? 0.f : x[i];
}

__device__ __forceinline__ void split_store(float v, __nv_bfloat16* hi, __nv_bfloat16* lo,
                                            size_t idx) {
    __nv_bfloat16 h = __float2bfloat16(v);
    hi[idx] = h;
    lo[idx] = __float2bfloat16(v - __bfloat162float(h));
}

// ---------------------------------------------------------------------------
// Fused prep: [0,4096) invMt split, [4096,8192) T split, [8192,12288) H split,
// [12288,20480) y split.  256 threads/block, 1 elem/thread.
// ---------------------------------------------------------------------------
__global__ void prep_kernel(const float* __restrict__ A,
                            const float* __restrict__ H,
                            const float* __restrict__ y,
                            const float* __restrict__ iwp,
                            const float* __restrict__ invM) {
    const int bid = blockIdx.x;
    if (bid < 4096) {
        size_t o = (size_t)bid * 256 + threadIdx.x;
        int k = (int)(o & (ND - 1));
        int n = (int)(o >> 10);
        split_store(invM[(size_t)k * ND + n], g_invMt_hi, g_invMt_lo, o);
    } else if (bid < 8192) {
        size_t o = (size_t)(bid - 4096) * 256 + threadIdx.x;
        int j = (int)(o & (ND - 1));
        int k = (int)(o >> 10);
        const float iw = *iwp;
        float v = 0.f;
        if (j == k)      v = (iw - 1.f) * A[(size_t)k * ND + k];
        else if (j > k)  v = -A[(size_t)k * ND + j];
        split_store(v, g_T_hi, g_T_lo, o);
    } else if (bid < 12288) {
        size_t o = (size_t)(bid - 8192) * 256 + threadIdx.x;
        split_store(H[o], g_H_hi, g_H_lo, o);
    } else {
        size_t o = (size_t)(bid - 12288) * 256 + threadIdx.x;
        split_store(y[o], g_y_hi, g_y_lo, o);
    }
}

// ---------------------------------------------------------------------------
// Fused: traj[0]=0 (blocks [0,2048), float4) | s0 split (blocks [2048,10240))
// ---------------------------------------------------------------------------
__global__ void s0zero_kernel(const float* __restrict__ A, float4* __restrict__ trajz) {
    const int bid = blockIdx.x;
    if (bid < 2048) {
        size_t i = (size_t)bid * 256 + threadIdx.x;
        trajz[i] = make_float4(0.f, 0.f, 0.f, 0.f);
    } else {
        size_t i = (size_t)(bid - 2048) * 256 + threadIdx.x;
        int col = (int)(i & (ND - 1));
        float v = g_yMF[i] / A[(size_t)col * ND + col];
        split_store(v, g_sA_hi, g_sA_lo, i);
    }
}

// ---------------------------------------------------------------------------
// mma.sync split-bf16 GEMM, 512 threads / 16 warps (4 per SMSP).
// Block tile 128x128, warp tile 32x32 (4x4 warp grid).
// K chunks of 32; 3-stage cp.async pipeline.
// ---------------------------------------------------------------------------
constexpr int CHUNK   = 32;
constexpr int NC      = KD / CHUNK;          // 32
constexpr int ROWB    = 80;                  // 64B data + 16B pad
constexpr int TILE_SM = 128 * ROWB;          // 10240 B
constexpr int STAGE_SM = 4 * TILE_SM;        // 40960 B
constexpr int NSTAGE  = 3;
constexpr int GEMM_SMEM = NSTAGE * STAGE_SM; // 122880 B

__global__ void __launch_bounds__(512, 1)
gemm_mma(const __nv_bfloat16* __restrict__ Ahi, const __nv_bfloat16* __restrict__ Alo,
         const __nv_bfloat16* __restrict__ Bhi, const __nv_bfloat16* __restrict__ Blo,
         const float* __restrict__ cAdd,
         float* __restrict__ outRow, float* __restrict__ outDual,
         __nv_bfloat16* __restrict__ outHi, __nv_bfloat16* __restrict__ outLo) {
    extern __shared__ char smem[];
    const uint32_t sb = smem_to_u32(smem);
    const int tid  = threadIdx.x;
    const int lane = tid & 31;
    const int w    = tid >> 5;          // 0..15
    const int wm   = w >> 2;            // 0..3
    const int wn   = w & 3;             // 0..3
    const int bm = blockIdx.y * 128;
    const int bn = blockIdx.x * 128;
    const int mo = wm * 32;
    const int no = wn * 32;

    // ---- global load addressing: 512 threads, 1 x 16B per tile each ----
    const int grow = tid >> 2;          // 0..127
    const int gg   = tid & 3;           // 16B group within 64B row
    const char* gsrc[4] = {
        (const char*)(Ahi + (size_t)(bm + grow) * KD),
        (const char*)(Alo + (size_t)(bm + grow) * KD),
        (const char*)(Bhi + (size_t)(bn + grow) * KD),
        (const char*)(Blo + (size_t)(bn + grow) * KD) };
    const uint32_t sdst = grow * ROWB + gg * 16;

    // ---- accumulators: warp tile 32x32 = 2 m16 x 4 n8 ----
    float acc[2][4][4];
    #pragma unroll
    for (int i = 0; i < 2; i++)
        #pragma unroll
        for (int j = 0; j < 4; j++)
            #pragma unroll
            for (int q = 0; q < 4; q++) acc[i][j][q] = 0.f;

    // ---- lane-constant ldmatrix offsets ----
    const int lt = lane >> 3, lr = lane & 7;
    const uint32_t aoff = (uint32_t)(((lt & 1) * 8 + lr) * ROWB + (lt >> 1) * 16);
    const uint32_t boff = (uint32_t)(((lt >> 1) * 8 + lr) * ROWB + (lt & 1) * 16);

    auto load_stage = [&](int s, int k0) {
        const uint32_t stage = sb + s * STAGE_SM;
        #pragma unroll
        for (int t = 0; t < 4; t++) {
            const char* g = gsrc[t] + (size_t)(k0 + gg * 8) * 2;
            cp_async16(stage + t * TILE_SM + sdst, g);
        }
    };

    load_stage(0, 0);  cp_async_commit();
    load_stage(1, CHUNK); cp_async_commit();

    #pragma unroll 1
    for (int i = 0; i < NC; i++) {
        cp_async_wait1();
        __syncthreads();

        const uint32_t stage = sb + (i % NSTAGE) * STAGE_SM;
        const uint32_t At_hi = stage + 0 * TILE_SM + mo * ROWB;
        const uint32_t At_lo = stage + 1 * TILE_SM + mo * ROWB;
        const uint32_t Bt_hi = stage + 2 * TILE_SM + no * ROWB;
        const uint32_t Bt_lo = stage + 3 * TILE_SM + no * ROWB;

        #pragma unroll
        for (int g2 = 0; g2 < 2; g2++) {       // two k16 steps per chunk
            uint32_t ah[2][4], al[2][4], bh[2][4], bl[2][4];
            #pragma unroll
            for (int mt = 0; mt < 2; mt++) {
                const uint32_t o = mt * 16 * ROWB + g2 * 32 + aoff;
                ldsm_x4(ah[mt][0], ah[mt][1], ah[mt][2], ah[mt][3], At_hi + o);
                ldsm_x4(al[mt][0], al[mt][1], al[mt][2], al[mt][3], At_lo + o);
            }
            #pragma unroll
            for (int np = 0; np < 2; np++) {
                const uint32_t o = np * 16 * ROWB + g2 * 32 + boff;
                ldsm_x4(bh[np][0], bh[np][1], bh[np][2], bh[np][3], Bt_hi + o);
                ldsm_x4(bl[np][0], bl[np][1], bl[np][2], bl[np][3], Bt_lo + o);
            }
            // 3 passes of 8 independent MMAs each
            #pragma unroll
            for (int np = 0; np < 2; np++)
                #pragma unroll
                for (int mt = 0; mt < 2; mt++)
                    #pragma unroll
                    for (int nt2 = 0; nt2 < 2; nt2++)
                        mma16816(acc[mt][np * 2 + nt2], ah[mt], &bh[np][nt2 * 2]);
            #pragma unroll
            for (int np = 0; np < 2; np++)
                #pragma unroll
                for (int mt = 0; mt < 2; mt++)
                    #pragma unroll
                    for (int nt2 = 0; nt2 < 2; nt2++)
                        mma16816(acc[mt][np * 2 + nt2], ah[mt], &bl[np][nt2 * 2]);
            #pragma unroll
            for (int np = 0; np < 2; np++)
                #pragma unroll
                for (int mt = 0; mt < 2; mt++)
                    #pragma unroll
                    for (int nt2 = 0; nt2 < 2; nt2++)
                        mma16816(acc[mt][np * 2 + nt2], al[mt], &bh[np][nt2 * 2]);
        }

        if (i + 2 < NC) load_stage((i + 2) % NSTAGE, (i + 2) * CHUNK);
        cp_async_commit();
    }
    __syncthreads();

    // ---- epilogue: per-warp 32x33 transpose buffer (67584 B < smem) ----
    float* buf = (float*)smem + w * (32 * 33);
    __syncwarp();
    #pragma unroll
    for (int mt = 0; mt < 2; mt++) {
        #pragma unroll
        for (int nt = 0; nt < 4; nt++) {
            const float* d = acc[mt][nt];
            const int r = mt * 16 + (lane >> 2);
            const int c = nt * 8 + (lane & 3) * 2;
            buf[r * 33 + c]           = d[0];
            buf[r * 33 + c + 1]       = d[1];
            buf[(r + 8) * 33 + c]     = d[2];
            buf[(r + 8) * 33 + c + 1] = d[3];
        }
    }
    __syncwarp();
    const int gc = bn + no + lane;
    #pragma unroll
    for (int rr = 0; rr < 32; rr++) {
        float v = buf[rr * 33 + lane];
        const size_t idx = (size_t)(bm + mo + rr) * ND + gc;
        if (cAdd) v += cAdd[idx];
        if (outRow)  outRow[idx]  = v;
        if (outDual) outDual[idx] = v;
        if (outHi) {
            __nv_bfloat16 hh = __float2bfloat16(v);
            outHi[idx] = hh;
            outLo[idx] = __float2bfloat16(v - __bfloat162float(hh));
        }
    }
}

// ---------------------------------------------------------------------------
// Launch sequence
// ---------------------------------------------------------------------------
extern "C" void kernel_launch(void* const* d_in, const int* in_sizes, int n_in,
                              void* d_out, int out_size) {
    const float* A  = (const float*)d_in[0];
    const float* H  = (const float*)d_in[1];
    const float* y  = (const float*)d_in[2];
    const float* iw = (const float*)d_in[3];

    float* out     = (float*)d_out;
    float* s_final = out;
    float* traj    = out + (size_t)BSZ * ND;

    cudaFuncSetAttribute(gemm_mma, cudaFuncAttributeMaxDynamicSharedMemorySize, GEMM_SMEM);

    float *invM, *yMF, *c;
    __nv_bfloat16 *invMt_hi, *invMt_lo, *T_hi, *T_lo, *H_hi, *H_lo, *V_hi, *V_lo;
    __nv_bfloat16 *y_hi, *y_lo, *yMF_hi, *yMF_lo, *sA_hi, *sA_lo, *sB_hi, *sB_lo;
    cudaGetSymbolAddress((void**)&invM,     g_invM);
    cudaGetSymbolAddress((void**)&yMF,      g_yMF);
    cudaGetSymbolAddress((void**)&c,        g_c);
    cudaGetSymbolAddress((void**)&invMt_hi, g_invMt_hi);
    cudaGetSymbolAddress((void**)&invMt_lo, g_invMt_lo);
    cudaGetSymbolAddress((void**)&T_hi,     g_T_hi);
    cudaGetSymbolAddress((void**)&T_lo,     g_T_lo);
    cudaGetSymbolAddress((void**)&H_hi,     g_H_hi);
    cudaGetSymbolAddress((void**)&H_lo,     g_H_lo);
    cudaGetSymbolAddress((void**)&V_hi,     g_V_hi);
    cudaGetSymbolAddress((void**)&V_lo,     g_V_lo);
    cudaGetSymbolAddress((void**)&y_hi,     g_y_hi);
    cudaGetSymbolAddress((void**)&y_lo,     g_y_lo);
    cudaGetSymbolAddress((void**)&yMF_hi,   g_yMF_hi);
    cudaGetSymbolAddress((void**)&yMF_lo,   g_yMF_lo);
    cudaGetSymbolAddress((void**)&sA_hi,    g_sA_hi);
    cudaGetSymbolAddress((void**)&sA_lo,    g_sA_lo);
    cudaGetSymbolAddress((void**)&sB_hi,    g_sB_hi);
    cudaGetSymbolAddress((void**)&sB_lo,    g_sB_lo);

    const dim3 gridB(ND / 128, BSZ / 128);   // 8 x 16 = 128 CTAs
    const dim3 gridS(ND / 128, ND / 128);    // 8 x 8  = 64 CTAs

    // 0: triangular inverse
    trinv_kernel<<<ND / 4, 128>>>(A, iw, invM);
    // 1: fused prep (invMt/T/H/y splits)
    prep_kernel<<<20480, 256>>>(A, H, y, iw, invM);
    // 2: yMF = y @ H^T  (fp32 + splits)
    gemm_mma<<<gridB, 512, GEMM_SMEM>>>(
        y_hi, y_lo, H_hi, H_lo, nullptr, yMF, nullptr, yMF_hi, yMF_lo);
    // 3: traj[0] = 0 ; s0 splits
    s0zero_kernel<<<10240, 256>>>(A, (float4*)traj);
    // 4: V[n][k] = W[k][n]  (splits only)
    gemm_mma<<<gridS, 512, GEMM_SMEM>>>(
        invMt_hi, invMt_lo, T_hi, T_lo, nullptr, nullptr, nullptr, V_hi, V_lo);
    // 5: c = yMF @ invM  (fp32)
    gemm_mma<<<gridB, 512, GEMM_SMEM>>>(
        yMF_hi, yMF_lo, invMt_hi, invMt_lo, nullptr, c, nullptr, nullptr, nullptr);

    // 6..30: main loop
    __nv_bfloat16 *srcHi = sA_hi, *srcLo = sA_lo, *dstHi = sB_hi, *dstLo = sB_lo;
    for (int t = 0; t < ITERS; t++) {
        float* outp = traj + (size_t)(t + 1) * BSZ * ND;
        float* dual = (t == ITERS - 1) ? s_final : nullptr;
        gemm_mma<<<gridB, 512, GEMM_SMEM>>>(
            srcHi, srcLo, V_hi, V_lo, c, outp, dual, dstHi, dstLo);
        __nv_bfloat16* th = srcHi; srcHi = dstHi; dstHi = th;
        __nv_bfloat16* tl = srcLo; srcLo = dstLo; dstLo = tl;
    }
}

// round 17
// speedup vs baseline: 3.5870x; 1.1292x over previous
#include <cuda_runtime.h>
#include <cuda_fp16.h>
#include <cstdint>

// ---------------------------------------------------------------------------
// Problem constants
// ---------------------------------------------------------------------------
constexpr int ND    = 1024;
constexpr int BSZ   = 2048;
constexpr int ITERS = 25;
constexpr int KD    = 1024;

// ---------------------------------------------------------------------------
// Helpers (baseline PTX only)
// ---------------------------------------------------------------------------
__device__ __forceinline__ uint32_t smem_to_u32(const void* p) {
    uint32_t a;
    asm("{ .reg .u64 t; cvta.to.shared.u64 t, %1; cvt.u32.u64 %0, t; }"
        : "=r"(a) : "l"(p));
    return a;
}
__device__ __forceinline__ void cp_async16(uint32_t sa, const void* g) {
    asm volatile("cp.async.cg.shared.global [%0], [%1], 16;" :: "r"(sa), "l"(g));
}
__device__ __forceinline__ void cp_async_commit() {
    asm volatile("cp.async.commit_group;" ::: "memory");
}
__device__ __forceinline__ void cp_async_wait1() {
    asm volatile("cp.async.wait_group 1;" ::: "memory");
}
__device__ __forceinline__ void ldsm_x4(uint32_t& r0, uint32_t& r1, uint32_t& r2,
                                        uint32_t& r3, uint32_t addr) {
    asm volatile("ldmatrix.sync.aligned.m8n8.x4.shared.b16 {%0,%1,%2,%3}, [%4];"
                 : "=r"(r0), "=r"(r1), "=r"(r2), "=r"(r3) : "r"(addr));
}
// fp16 x fp16 -> fp32 accumulate (baseline sm_80 PTX)
__device__ __forceinline__ void mma16816(float* d, const uint32_t* a, const uint32_t* b) {
    asm volatile(
        "mma.sync.aligned.m16n8k16.row.col.f32.f16.f16.f32 "
        "{%0,%1,%2,%3},{%4,%5,%6,%7},{%8,%9},{%0,%1,%2,%3};"
        : "+f"(d[0]), "+f"(d[1]), "+f"(d[2]), "+f"(d[3])
        : "r"(a[0]), "r"(a[1]), "r"(a[2]), "r"(a[3]), "r"(b[0]), "r"(b[1]));
}

// ---------------------------------------------------------------------------
// Scratch (device globals)
// ---------------------------------------------------------------------------
__device__ float g_invM[ND * ND];
__device__ float g_yMF [BSZ * ND];
__device__ float g_c   [BSZ * ND];
__device__ __half g_invMt_hi[ND * ND],  g_invMt_lo[ND * ND];
__device__ __half g_T_hi    [ND * ND],  g_T_lo    [ND * ND];
__device__ __half g_H_hi    [ND * ND],  g_H_lo    [ND * ND];
__device__ __half g_V_hi    [ND * ND],  g_V_lo    [ND * ND];
__device__ __half g_y_hi    [BSZ * ND], g_y_lo    [BSZ * ND];
__device__ __half g_yMF_hi  [BSZ * ND], g_yMF_lo  [BSZ * ND];
__device__ __half g_sA      [BSZ * ND];     // fp16 round of current s
__device__ __half g_sB      [BSZ * ND];

// ---------------------------------------------------------------------------
// trinv: column-parallel forward substitution for inv(iw*D + L)
// ---------------------------------------------------------------------------
__global__ void trinv_kernel(const float* __restrict__ A,
                             const float* __restrict__ iwp,
                             float* __restrict__ invM) {
    __shared__ float xs[4][ND];
    const int warp = threadIdx.x >> 5;
    const int lane = threadIdx.x & 31;
    const int j = blockIdx.x * 4 + warp;
    const float iw = *iwp;
    float* x = xs[warp];
    if (lane == 0) x[j] = 1.0f / (iw * A[(size_t)j * ND + j]);
    __syncwarp();
    for (int i = j + 1; i < ND; i++) {
        const float* Ai = A + (size_t)i * ND;
        float sum = 0.f;
        for (int k = j + lane; k < i; k += 32) sum += Ai[k] * x[k];
        #pragma unroll
        for (int o = 16; o > 0; o >>= 1) sum += __shfl_xor_sync(0xffffffffu, sum, o);
        if (lane == 0) x[i] = -sum / (iw * Ai[i]);
        __syncwarp();
    }
    for (int i = lane; i < ND; i += 32)
        invM[(size_t)i * ND + j] = (i < j) ? 0.f : x[i];
}

__device__ __forceinline__ void split_store_h(float v, __half* hi, __half* lo,
                                              size_t idx) {
    __half h = __float2half(v);
    hi[idx] = h;
    lo[idx] = __float2half(v - __half2float(h));
}

// ---------------------------------------------------------------------------
// Fused prep: [0,4096) invMt split, [4096,8192) T split, [8192,12288) H split,
// [12288,20480) y split.  256 threads/block, fp16 hi/lo splits.
// ---------------------------------------------------------------------------
__global__ void prep_kernel(const float* __restrict__ A,
                            const float* __restrict__ H,
                            const float* __restrict__ y,
                            const float* __restrict__ iwp,
                            const float* __restrict__ invM) {
    const int bid = blockIdx.x;
    if (bid < 4096) {
        size_t o = (size_t)bid * 256 + threadIdx.x;
        int k = (int)(o & (ND - 1));
        int n = (int)(o >> 10);
        split_store_h(invM[(size_t)k * ND + n], g_invMt_hi, g_invMt_lo, o);
    } else if (bid < 8192) {
        size_t o = (size_t)(bid - 4096) * 256 + threadIdx.x;
        int j = (int)(o & (ND - 1));
        int k = (int)(o >> 10);
        const float iw = *iwp;
        float v = 0.f;
        if (j == k)      v = (iw - 1.f) * A[(size_t)k * ND + k];
        else if (j > k)  v = -A[(size_t)k * ND + j];
        split_store_h(v, g_T_hi, g_T_lo, o);
    } else if (bid < 12288) {
        size_t o = (size_t)(bid - 8192) * 256 + threadIdx.x;
        split_store_h(H[o], g_H_hi, g_H_lo, o);
    } else {
        size_t o = (size_t)(bid - 12288) * 256 + threadIdx.x;
        split_store_h(y[o], g_y_hi, g_y_lo, o);
    }
}

// ---------------------------------------------------------------------------
// Fused: traj[0]=0 (blocks [0,2048), float4) | s0 fp16 (blocks [2048,10240))
// ---------------------------------------------------------------------------
__global__ void s0zero_kernel(const float* __restrict__ A, float4* __restrict__ trajz) {
    const int bid = blockIdx.x;
    if (bid < 2048) {
        size_t i = (size_t)bid * 256 + threadIdx.x;
        trajz[i] = make_float4(0.f, 0.f, 0.f, 0.f);
    } else {
        size_t i = (size_t)(bid - 2048) * 256 + threadIdx.x;
        int col = (int)(i & (ND - 1));
        float v = g_yMF[i] / A[(size_t)col * ND + col];
        g_sA[i] = __float2half(v);
    }
}

// ---------------------------------------------------------------------------
// mma.sync split-fp16 GEMM, 512 threads / 16 warps, tile 128x128, warp 32x32.
// TWO=false (3-term): D = Ah*Bh + Ah*Bl + Al*Bh   (tiles: Ah,Al,Bh,Bl)
// TWO=true  (2-term): D = Ah*Bh + Ah*Bl = Ah*(B)  (tiles: Ah,Bh,Bl)
// K chunks of 32; 3-stage cp.async pipeline. All template branching is
// if constexpr (no UB in discarded branches).
// ---------------------------------------------------------------------------
constexpr int CHUNK   = 32;
constexpr int NC      = KD / CHUNK;          // 32
constexpr int ROWB    = 80;                  // 64B data + 16B pad
constexpr int TILE_SM = 128 * ROWB;          // 10240 B
constexpr int NSTAGE  = 3;
constexpr int SMEM_3T = NSTAGE * 4 * TILE_SM;   // 122880
constexpr int SMEM_2T = NSTAGE * 3 * TILE_SM;   //  92160

template <bool TWO>
__global__ void __launch_bounds__(512, 1)
gemm_mma(const __half* __restrict__ A0, const __half* __restrict__ A1,
         const __half* __restrict__ B0, const __half* __restrict__ B1,
         const float* __restrict__ cAdd,
         float* __restrict__ outRow, float* __restrict__ outDual,
         __half* __restrict__ outHi, __half* __restrict__ outLo) {
    constexpr int NTILES   = TWO ? 3 : 4;
    constexpr int STAGE_SM = NTILES * TILE_SM;
    extern __shared__ char smem[];
    const uint32_t sb = smem_to_u32(smem);
    const int tid  = threadIdx.x;
    const int lane = tid & 31;
    const int w    = tid >> 5;          // 0..15
    const int wm   = w >> 2;            // 0..3
    const int wn   = w & 3;             // 0..3
    const int bm = blockIdx.y * 128;
    const int bn = blockIdx.x * 128;
    const int mo = wm * 32;
    const int no = wn * 32;

    // ---- global load addressing: 512 threads, 1 x 16B per tile each ----
    const int grow = tid >> 2;          // 0..127
    const int gg   = tid & 3;           // 16B group within 64B row
    const char* gsrc[4];                // fixed size 4: no OOB in any branch
    gsrc[0] = (const char*)(A0 + (size_t)(bm + grow) * KD);
    if constexpr (TWO) {
        gsrc[1] = (const char*)(B0 + (size_t)(bn + grow) * KD);
        gsrc[2] = (const char*)(B1 + (size_t)(bn + grow) * KD);
        gsrc[3] = nullptr;
    } else {
        gsrc[1] = (const char*)(A1 + (size_t)(bm + grow) * KD);
        gsrc[2] = (const char*)(B0 + (size_t)(bn + grow) * KD);
        gsrc[3] = (const char*)(B1 + (size_t)(bn + grow) * KD);
    }
    const uint32_t sdst = grow * ROWB + gg * 16;

    // ---- accumulators: warp tile 32x32 = 2 m16 x 4 n8 ----
    float acc[2][4][4];
    #pragma unroll
    for (int i = 0; i < 2; i++)
        #pragma unroll
        for (int j = 0; j < 4; j++)
            #pragma unroll
            for (int q = 0; q < 4; q++) acc[i][j][q] = 0.f;

    // ---- lane-constant ldmatrix offsets ----
    const int lt = lane >> 3, lr = lane & 7;
    const uint32_t aoff = (uint32_t)(((lt & 1) * 8 + lr) * ROWB + (lt >> 1) * 16);
    const uint32_t boff = (uint32_t)(((lt >> 1) * 8 + lr) * ROWB + (lt & 1) * 16);

    auto load_stage = [&](int s, int k0) {
        const uint32_t stage = sb + s * STAGE_SM;
        #pragma unroll
        for (int t = 0; t < NTILES; t++) {
            const char* g = gsrc[t] + (size_t)(k0 + gg * 8) * 2;
            cp_async16(stage + t * TILE_SM + sdst, g);
        }
    };

    load_stage(0, 0);  cp_async_commit();
    load_stage(1, CHUNK); cp_async_commit();

    #pragma unroll 1
    for (int i = 0; i < NC; i++) {
        cp_async_wait1();
        __syncthreads();

        const uint32_t stage = sb + (i % NSTAGE) * STAGE_SM;
        const uint32_t At_hi = stage + mo * ROWB;
        const uint32_t Bt_hi = stage + (TWO ? 1 : 2) * TILE_SM + no * ROWB;
        const uint32_t Bt_lo = stage + (TWO ? 2 : 3) * TILE_SM + no * ROWB;

        #pragma unroll
        for (int g2 = 0; g2 < 2; g2++) {       // two k16 steps per chunk
            uint32_t ah[2][4], al[2][4], bh[2][4], bl[2][4];
            #pragma unroll
            for (int mt = 0; mt < 2; mt++) {
                const uint32_t o = mt * 16 * ROWB + g2 * 32 + aoff;
                ldsm_x4(ah[mt][0], ah[mt][1], ah[mt][2], ah[mt][3], At_hi + o);
                if constexpr (!TWO) {
                    const uint32_t At_lo = stage + 1 * TILE_SM + mo * ROWB;
                    ldsm_x4(al[mt][0], al[mt][1], al[mt][2], al[mt][3], At_lo + o);
                }
            }
            #pragma unroll
            for (int np = 0; np < 2; np++) {
                const uint32_t o = np * 16 * ROWB + g2 * 32 + boff;
                ldsm_x4(bh[np][0], bh[np][1], bh[np][2], bh[np][3], Bt_hi + o);
                ldsm_x4(bl[np][0], bl[np][1], bl[np][2], bl[np][3], Bt_lo + o);
            }
            // pass 1: Ah*Bh (8 independent MMAs)
            #pragma unroll
            for (int np = 0; np < 2; np++)
                #pragma unroll
                for (int mt = 0; mt < 2; mt++)
                    #pragma unroll
                    for (int nt2 = 0; nt2 < 2; nt2++)
                        mma16816(acc[mt][np * 2 + nt2], ah[mt], &bh[np][nt2 * 2]);
            // pass 2: Ah*Bl
            #pragma unroll
            for (int np = 0; np < 2; np++)
                #pragma unroll
                for (int mt = 0; mt < 2; mt++)
                    #pragma unroll
                    for (int nt2 = 0; nt2 < 2; nt2++)
                        mma16816(acc[mt][np * 2 + nt2], ah[mt], &bl[np][nt2 * 2]);
            // pass 3 (3-term only): Al*Bh
            if constexpr (!TWO) {
                #pragma unroll
                for (int np = 0; np < 2; np++)
                    #pragma unroll
                    for (int mt = 0; mt < 2; mt++)
                        #pragma unroll
                        for (int nt2 = 0; nt2 < 2; nt2++)
                            mma16816(acc[mt][np * 2 + nt2], al[mt], &bh[np][nt2 * 2]);
            }
        }

        if (i + 2 < NC) load_stage((i + 2) % NSTAGE, (i + 2) * CHUNK);
        cp_async_commit();
    }
    __syncthreads();

    // ---- epilogue: per-warp 32x33 transpose buffer (67584 B < smem) ----
    float* buf = (float*)smem + w * (32 * 33);
    __syncwarp();
    #pragma unroll
    for (int mt = 0; mt < 2; mt++) {
        #pragma unroll
        for (int nt = 0; nt < 4; nt++) {
            const float* d = acc[mt][nt];
            const int r = mt * 16 + (lane >> 2);
            const int c = nt * 8 + (lane & 3) * 2;
            buf[r * 33 + c]           = d[0];
            buf[r * 33 + c + 1]       = d[1];
            buf[(r + 8) * 33 + c]     = d[2];
            buf[(r + 8) * 33 + c + 1] = d[3];
        }
    }
    __syncwarp();
    const int gc = bn + no + lane;
    #pragma unroll
    for (int rr = 0; rr < 32; rr++) {
        float v = buf[rr * 33 + lane];
        const size_t idx = (size_t)(bm + mo + rr) * ND + gc;
        if (cAdd) v += cAdd[idx];
        if (outRow)  outRow[idx]  = v;
        if (outDual) outDual[idx] = v;
        if (outHi) {
            __half hh = __float2half(v);
            outHi[idx] = hh;
            if (outLo) outLo[idx] = __float2half(v - __half2float(hh));
        }
    }
}

// ---------------------------------------------------------------------------
// Launch sequence
// ---------------------------------------------------------------------------
extern "C" void kernel_launch(void* const* d_in, const int* in_sizes, int n_in,
                              void* d_out, int out_size) {
    const float* A  = (const float*)d_in[0];
    const float* H  = (const float*)d_in[1];
    const float* y  = (const float*)d_in[2];
    const float* iw = (const float*)d_in[3];

    float* out     = (float*)d_out;
    float* s_final = out;
    float* traj    = out + (size_t)BSZ * ND;

    cudaFuncSetAttribute(gemm_mma<false>, cudaFuncAttributeMaxDynamicSharedMemorySize, SMEM_3T);
    cudaFuncSetAttribute(gemm_mma<true>,  cudaFuncAttributeMaxDynamicSharedMemorySize, SMEM_2T);

    float *invM, *yMF, *c;
    __half *invMt_hi, *invMt_lo, *T_hi, *T_lo, *H_hi, *H_lo, *V_hi, *V_lo;
    __half *y_hi, *y_lo, *yMF_hi, *yMF_lo, *sA, *sB;
    cudaGetSymbolAddress((void**)&invM,     g_invM);
    cudaGetSymbolAddress((void**)&yMF,      g_yMF);
    cudaGetSymbolAddress((void**)&c,        g_c);
    cudaGetSymbolAddress((void**)&invMt_hi, g_invMt_hi);
    cudaGetSymbolAddress((void**)&invMt_lo, g_invMt_lo);
    cudaGetSymbolAddress((void**)&T_hi,     g_T_hi);
    cudaGetSymbolAddress((void**)&T_lo,     g_T_lo);
    cudaGetSymbolAddress((void**)&H_hi,     g_H_hi);
    cudaGetSymbolAddress((void**)&H_lo,     g_H_lo);
    cudaGetSymbolAddress((void**)&V_hi,     g_V_hi);
    cudaGetSymbolAddress((void**)&V_lo,     g_V_lo);
    cudaGetSymbolAddress((void**)&y_hi,     g_y_hi);
    cudaGetSymbolAddress((void**)&y_lo,     g_y_lo);
    cudaGetSymbolAddress((void**)&yMF_hi,   g_yMF_hi);
    cudaGetSymbolAddress((void**)&yMF_lo,   g_yMF_lo);
    cudaGetSymbolAddress((void**)&sA,       g_sA);
    cudaGetSymbolAddress((void**)&sB,       g_sB);

    const dim3 gridB(ND / 128, BSZ / 128);   // 8 x 16 = 128 CTAs
    const dim3 gridS(ND / 128, ND / 128);    // 8 x 8  = 64 CTAs

    // 0: triangular inverse
    trinv_kernel<<<ND / 4, 128>>>(A, iw, invM);
    // 1: fused prep (invMt/T/H/y fp16 splits)
    prep_kernel<<<20480, 256>>>(A, H, y, iw, invM);
    // 2: yMF = y @ H^T  (3-term; fp32 + fp16 splits)
    gemm_mma<false><<<gridB, 512, SMEM_3T>>>(
        y_hi, y_lo, H_hi, H_lo, nullptr, yMF, nullptr, yMF_hi, yMF_lo);
    // 3: traj[0] = 0 ; s0 -> fp16
    s0zero_kernel<<<10240, 256>>>(A, (float4*)traj);
    // 4: V[n][k] = W[k][n]  (3-term; fp16 hi/lo split only)
    gemm_mma<false><<<gridS, 512, SMEM_3T>>>(
        invMt_hi, invMt_lo, T_hi, T_lo, nullptr, nullptr, nullptr, V_hi, V_lo);
    // 5: c = yMF @ invM  (3-term; fp32)
    gemm_mma<false><<<gridB, 512, SMEM_3T>>>(
        yMF_hi, yMF_lo, invMt_hi, invMt_lo, nullptr, c, nullptr, nullptr, nullptr);

    // 6..30: main loop — 2-term: traj[t+1] = fp16(s_t) @ (Vh+Vl) + c
    __half *src = sA, *dst = sB;
    for (int t = 0; t < ITERS; t++) {
        float* outp = traj + (size_t)(t + 1) * BSZ * ND;
        float* dual = (t == ITERS - 1) ? s_final : nullptr;
        gemm_mma<true><<<gridB, 512, SMEM_2T>>>(
            src, nullptr, V_hi, V_lo, c, outp, dual, dst, nullptr);
        __half* tmp = src; src = dst; dst = tmp;
    }
}